// round 14
// baseline (speedup 1.0000x reference)
#include <cuda_runtime.h>
#include <cuda_bf16.h>
#include <cuda_fp16.h>
#include <cstdint>

#define N_NODES 50000
#define N_PAD   50048      // padded to multiple of 128
#define N_EDGES 800000
#define D_F 256
#define D_H 512
#define D_O 256
#define D_AB 1024

// ---------------- scratch (static device allocations; no cudaMalloc) -------
__device__ uint32_t g_Xh[N_PAD * (D_F / 2)];       // packed fp16 x hi
__device__ uint32_t g_Xl[N_PAD * (D_F / 2)];       // packed fp16 x lo (residual)
__device__ uint32_t g_W1h[D_AB * (D_F / 2)];       // packed fp16 Wcat (single)
__device__ uint32_t g_W2h[D_O * (D_H / 2)];        // packed fp16 W2 (single)
__device__ float    g_bias1[D_AB];
__device__ float    g_Apart[N_PAD * D_H];          // 102.4 MB fp32 (A part)
__device__ uint32_t g_Bh[N_PAD * (D_H / 2)];       // 51.2 MB packed fp16 (B part)
__device__ uint32_t g_Sh[N_PAD * (D_H / 2)];       // S single fp16
__device__ int      g_counts[N_NODES];
__device__ int      g_offsets[N_NODES + 1];
__device__ int      g_cursor[N_NODES];
__device__ int      g_scol[N_EDGES];
__device__ int      g_idx64;

// ---------------- helpers ---------------------------------------------------
__device__ __forceinline__ uint32_t h2_as_u32(__half2 h) {
    uint32_t u; *(__half2*)&u = h; return u;
}
__device__ __forceinline__ float2 u32_as_f2(uint32_t u) {
    __half2 h = *(__half2*)&u;
    return __half22float2(h);
}
__device__ __forceinline__ void split2h(float v0, float v1, uint32_t& hw, uint32_t& lw) {
    __half2 hh = __floats2half2_rn(v0, v1);
    float2 back = __half22float2(hh);
    __half2 ll = __floats2half2_rn(v0 - back.x, v1 - back.y);
    hw = h2_as_u32(hh);
    lw = h2_as_u32(ll);
}
__device__ __forceinline__ uint32_t pack2h(float v0, float v1) {
    return h2_as_u32(__floats2half2_rn(v0, v1));
}
__device__ __forceinline__ void mma_f16(float* d, const uint32_t* a, const uint32_t* b) {
    asm volatile(
        "mma.sync.aligned.m16n8k16.row.col.f32.f16.f16.f32 "
        "{%0,%1,%2,%3}, {%4,%5,%6,%7}, {%8,%9}, {%0,%1,%2,%3};\n"
        : "+f"(d[0]), "+f"(d[1]), "+f"(d[2]), "+f"(d[3])
        : "r"(a[0]), "r"(a[1]), "r"(a[2]), "r"(a[3]), "r"(b[0]), "r"(b[1]));
}
__device__ __forceinline__ void ldsm_x4(uint32_t* r, uint32_t saddr) {
    asm volatile("ldmatrix.sync.aligned.m8n8.x4.shared.b16 {%0,%1,%2,%3}, [%4];"
                 : "=r"(r[0]), "=r"(r[1]), "=r"(r[2]), "=r"(r[3]) : "r"(saddr));
}
__device__ __forceinline__ uint32_t smem_u32(const void* p) {
    uint32_t a;
    asm("{ .reg .u64 t; cvta.to.shared.u64 t, %1; cvt.u32.u64 %0, t; }" : "=r"(a) : "l"(p));
    return a;
}
#define CP16(dst, src) \
    asm volatile("cp.async.cg.shared.global [%0], [%1], 16;" :: "r"(dst), "l"(src))
#define CP_COMMIT() asm volatile("cp.async.commit_group;" ::: "memory")
#define CP_WAIT0()  asm volatile("cp.async.wait_group 0;" ::: "memory")

// ---------------- edge-index dtype detection -------------------------------
__global__ void detect_dtype_kernel(const unsigned* ei) {
    unsigned acc = 0;
    for (int k = threadIdx.x; k < 512; k += 32) acc |= ei[2 * k + 1];
    #pragma unroll
    for (int o = 16; o > 0; o >>= 1) acc |= __shfl_xor_sync(0xFFFFFFFFu, acc, o);
    if (threadIdx.x == 0) g_idx64 = (acc == 0) ? 1 : 0;
}
__device__ __forceinline__ int load_eidx(const void* ei, int is64, long long pos) {
    return is64 ? (int)((const long long*)ei)[pos] : ((const int*)ei)[pos];
}

// ---------------- x split: fp32 -> packed fp16 hi/lo ------------------------
__global__ void split_x_kernel(const float* __restrict__ x) {
    int gid = blockIdx.x * blockDim.x + threadIdx.x;
    if (gid >= N_NODES * 32) return;
    int row = gid >> 5, ch = gid & 31;
    const float4* p = (const float4*)(x + (size_t)row * D_F + ch * 8);
    float4 v0 = p[0], v1 = p[1];
    uint4 h, l;
    split2h(v0.x, v0.y, h.x, l.x); split2h(v0.z, v0.w, h.y, l.y);
    split2h(v1.x, v1.y, h.z, l.z); split2h(v1.z, v1.w, h.w, l.w);
    *(uint4*)(g_Xh + (size_t)row * (D_F / 2) + ch * 4) = h;
    *(uint4*)(g_Xl + (size_t)row * (D_F / 2) + ch * 4) = l;
}

// ---------------- weight prep: K-major packed fp16 (single) ----------------
__global__ void build_w1t_kernel(const float* __restrict__ W1, const float* __restrict__ b1) {
    int idx = blockIdx.x * blockDim.x + threadIdx.x;
    if (idx < D_AB * (D_F / 2)) {
        int n  = idx >> 7;
        int kw = idx & 127;
        int k0 = kw * 2;
        float v0, v1;
        if (n < D_H) {
            v0 = W1[k0 * D_H + n]       - W1[(k0 + D_F) * D_H + n];
            v1 = W1[(k0 + 1) * D_H + n] - W1[(k0 + 1 + D_F) * D_H + n];
        } else {
            v0 = W1[(k0 + D_F) * D_H + (n - D_H)];
            v1 = W1[(k0 + 1 + D_F) * D_H + (n - D_H)];
        }
        g_W1h[idx] = pack2h(v0, v1);
    }
    if (idx < D_AB) g_bias1[idx] = (idx < D_H) ? b1[idx] : 0.f;
}
__global__ void build_w2t_kernel(const float* __restrict__ W2) {
    int idx = blockIdx.x * blockDim.x + threadIdx.x;
    if (idx < D_O * (D_H / 2)) {
        int n  = idx >> 8;
        int kw = idx & 255;
        g_W2h[idx] = pack2h(W2[(2 * kw) * D_O + n], W2[(2 * kw + 1) * D_O + n]);
    }
}

// ---------------- counting sort of edges by center node --------------------
__global__ void hist_kernel(const void* __restrict__ ei) {
    int e = blockIdx.x * blockDim.x + threadIdx.x;
    if (e >= N_EDGES) return;
    int r = load_eidx(ei, g_idx64, e);
    atomicAdd(&g_counts[r], 1);
}
__global__ void scan_kernel() {
    __shared__ int sh[1024];
    const int PER = 49;
    int t = threadIdx.x;
    int base = t * PER;
    int sum = 0;
    for (int j = 0; j < PER; j++) {
        int idx = base + j;
        if (idx < N_NODES) sum += g_counts[idx];
    }
    sh[t] = sum;
    __syncthreads();
    #pragma unroll
    for (int off = 1; off < 1024; off <<= 1) {
        int add = (t >= off) ? sh[t - off] : 0;
        __syncthreads();
        sh[t] += add;
        __syncthreads();
    }
    int run = sh[t] - sum;
    for (int j = 0; j < PER; j++) {
        int idx = base + j;
        if (idx < N_NODES) {
            g_offsets[idx] = run;
            g_cursor[idx]  = run;
            run += g_counts[idx];
        }
    }
    if (t == 1023) g_offsets[N_NODES] = run;
}
__global__ void scatter_kernel(const void* __restrict__ ei) {
    int e = blockIdx.x * blockDim.x + threadIdx.x;
    if (e >= N_EDGES) return;
    int is64 = g_idx64;
    int r = load_eidx(ei, is64, e);
    int c = load_eidx(ei, is64, (long long)N_EDGES + e);
    int pos = atomicAdd(&g_cursor[r], 1);
    g_scol[pos] = c;
}

// =========== fp16 GEMM, BK=64: A 1- or 2-term hi/lo, W single fp16 =========
// C = (Ah[+Al]) @ W^T. 2-stage cp.async pipeline (R6-proven structure),
// chunk doubled to 64 K-elems (32 words) -> half the sync boundaries.
// Row stride 36 words (144 B): 16*r mod 128 covers all 8 chunks (R9-validated).
// mode 0 (GEMM1): cols < 512 -> fp32 C, cols >= 512 -> packed fp16 Cb.
// mode 1 (GEMM2): fp32 C with deg*bias.
#define KWC 32                           // words per row per chunk (K=64)
#define STW 36
#define TILE_W (128 * STW)               // 4608 words
#define STAGE_W (3 * TILE_W)             // 13824 words
#define CSTRIDE 132
#define GEMM_DYNSMEM (2 * STAGE_W * 4)   // 110592 B

__global__ void __launch_bounds__(256, 2) tc_gemm_kernel(
    const uint32_t* __restrict__ Ah, const uint32_t* __restrict__ Al,
    const uint32_t* __restrict__ Bs,
    float* __restrict__ C, uint32_t* __restrict__ Cb,
    int M, int K, int ldc,
    const float* __restrict__ bias, int mode, int aTwo)
{
    extern __shared__ uint32_t smw[];
    int tid = threadIdx.x;
    int wid = tid >> 5;
    int lane = tid & 31;
    int warpM = wid & 1;
    int warpN = wid >> 1;
    int blockRow = blockIdx.y * 128;
    int blockCol = blockIdx.x * 128;
    const int Kw = K >> 1;
    const int nch = K >> 6;

    float acc[4][4][4];
    #pragma unroll
    for (int mt = 0; mt < 4; mt++)
        #pragma unroll
        for (int nt = 0; nt < 4; nt++)
            #pragma unroll
            for (int r = 0; r < 4; r++) acc[mt][nt][r] = 0.f;

    uint32_t sbase = smem_u32(smw);
    int ldRow = tid >> 1;
    int ldHalf = tid & 1;                       // each thread: 16 words of one row
    uint32_t soB = (uint32_t)(ldRow * STW + ldHalf * 16) * 4;
    size_t aOff = (size_t)(blockRow + ldRow) * Kw + ldHalf * 16;
    size_t bOff = (size_t)(blockCol + ldRow) * Kw + ldHalf * 16;

    auto issue = [&](int c) {
        uint32_t d = sbase + (uint32_t)(c & 1) * (STAGE_W * 4) + soB;
        const uint32_t* a0 = Ah + aOff + (size_t)c * KWC;
        const uint32_t* b0 = Bs + bOff + (size_t)c * KWC;
        CP16(d, a0);       CP16(d + 16, a0 + 4);
        CP16(d + 32, a0 + 8); CP16(d + 48, a0 + 12);
        if (aTwo) {
            const uint32_t* a1 = Al + aOff + (size_t)c * KWC;
            uint32_t dl = d + TILE_W * 4;
            CP16(dl, a1);       CP16(dl + 16, a1 + 4);
            CP16(dl + 32, a1 + 8); CP16(dl + 48, a1 + 12);
        }
        uint32_t db = d + 2 * TILE_W * 4;
        CP16(db, b0);       CP16(db + 16, b0 + 4);
        CP16(db + 32, b0 + 8); CP16(db + 48, b0 + 12);
        CP_COMMIT();
    };

    issue(0);
    CP_WAIT0();
    __syncthreads();

    int aLaneRow = (lane & 7) + ((lane >> 3) & 1) * 8;
    int aLaneColW = (lane >> 4) * 4;
    int bLaneRow = (lane & 7) + (lane >> 4) * 8;
    int bLaneColW = ((lane >> 3) & 1) * 4;
    uint32_t aAddr0 = sbase + ((warpM * 64 + aLaneRow) * STW + aLaneColW) * 4;
    uint32_t bAddr0 = sbase + ((warpN * 32 + bLaneRow) * STW + bLaneColW) * 4
                      + 2 * TILE_W * 4;

    for (int c = 0; c < nch; c++) {
        if (c + 1 < nch) issue(c + 1);

        uint32_t stageOff = (uint32_t)(c & 1) * (STAGE_W * 4);
        #pragma unroll
        for (int ks = 0; ks < 4; ks++) {
            uint32_t kOff = stageOff + ks * 32;
            uint32_t ah[4][4], al[4][4], bs[2][4];
            #pragma unroll
            for (int mt = 0; mt < 4; mt++) {
                uint32_t a = aAddr0 + kOff + mt * (16 * STW * 4);
                ldsm_x4(ah[mt], a);
                if (aTwo) ldsm_x4(al[mt], a + TILE_W * 4);
            }
            #pragma unroll
            for (int p = 0; p < 2; p++) {
                uint32_t b = bAddr0 + kOff + p * (16 * STW * 4);
                ldsm_x4(bs[p], b);
            }
            #pragma unroll
            for (int mt = 0; mt < 4; mt++)
                #pragma unroll
                for (int nt = 0; nt < 4; nt++) {
                    const uint32_t* bh = &bs[nt >> 1][(nt & 1) * 2];
                    mma_f16(acc[mt][nt], ah[mt], bh);
                    if (aTwo) mma_f16(acc[mt][nt], al[mt], bh);
                }
        }

        if (c + 1 < nch) {
            CP_WAIT0();
            __syncthreads();
        }
    }

    // ---- staged epilogue: acc -> smem (fp32) -> coalesced gmem ----
    __syncthreads();
    float* cs = (float*)smw;
    #pragma unroll
    for (int mt = 0; mt < 4; mt++) {
        int r0 = warpM * 64 + mt * 16 + (lane >> 2);
        #pragma unroll
        for (int nt = 0; nt < 4; nt++) {
            int col = warpN * 32 + nt * 8 + (lane & 3) * 2;
            *(float2*)(cs + r0 * CSTRIDE + col) = make_float2(acc[mt][nt][0], acc[mt][nt][1]);
            *(float2*)(cs + (r0 + 8) * CSTRIDE + col) = make_float2(acc[mt][nt][2], acc[mt][nt][3]);
        }
    }
    __syncthreads();
    #pragma unroll
    for (int kk = 0; kk < 16; kk++) {
        int idx = tid + kk * 256;
        int row = idx >> 5;
        int c4 = (idx & 31) * 4;
        int gr = blockRow + row;
        if (gr < M) {
            float4 v = *(float4*)(cs + row * CSTRIDE + c4);
            int col = blockCol + c4;
            float4 bv = *(const float4*)(bias + col);
            if (mode == 0) {
                v.x += bv.x; v.y += bv.y; v.z += bv.z; v.w += bv.w;
                if (col < D_H) {
                    *(float4*)(C + (size_t)gr * ldc + col) = v;
                } else {
                    uint32_t w0 = h2_as_u32(__floats2half2_rn(v.x, v.y));
                    uint32_t w1 = h2_as_u32(__floats2half2_rn(v.z, v.w));
                    *(uint2*)(Cb + (size_t)gr * (D_H / 2) + ((col - D_H) >> 1)) =
                        make_uint2(w0, w1);
                }
            } else {
                float degf = (float)(g_offsets[gr + 1] - g_offsets[gr]);
                v.x += degf * bv.x; v.y += degf * bv.y;
                v.z += degf * bv.z; v.w += degf * bv.w;
                *(float4*)(C + (size_t)gr * ldc + col) = v;
            }
        }
    }
}

// ---------------- aggregation: 2 warps per node, fp16 B gathers -------------
// output: single fp16 packed S
__global__ void __launch_bounds__(256) aggregate_kernel() {
    int gwarp = (blockIdx.x * blockDim.x + threadIdx.x) >> 5;
    int node = gwarp >> 1;
    int half = gwarp & 1;
    int lane = threadIdx.x & 31;
    if (node >= N_NODES) return;

    const float* Abase = g_Apart + (size_t)node * D_H + half * 256 + lane * 8;
    float4 a0 = *(const float4*)Abase;
    float4 a1 = *(const float4*)(Abase + 4);
    float4 s0 = make_float4(0, 0, 0, 0), s1 = s0;

    const size_t bcolw = (size_t)(half * 128 + lane * 4);
    int beg = g_offsets[node], end = g_offsets[node + 1];

    for (int b = beg; b < end; b += 32) {
        int jv = (b + lane < end) ? g_scol[b + lane] : 0;
        int cnt = min(32, end - b);
        int t = 0;
        for (; t + 7 < cnt; t += 8) {
            uint4 pw[8];
            #pragma unroll
            for (int u = 0; u < 8; u++) {
                int j = __shfl_sync(0xFFFFFFFFu, jv, t + u);
                pw[u] = *(const uint4*)(g_Bh + (size_t)j * (D_H / 2) + bcolw);
            }
            #pragma unroll
            for (int u = 0; u < 8; u++) {
                float2 f0 = u32_as_f2(pw[u].x);
                float2 f1 = u32_as_f2(pw[u].y);
                float2 f2 = u32_as_f2(pw[u].z);
                float2 f3 = u32_as_f2(pw[u].w);
                s0.x += fmaxf(a0.x + f0.x, 0.f);
                s0.y += fmaxf(a0.y + f0.y, 0.f);
                s0.z += fmaxf(a0.z + f1.x, 0.f);
                s0.w += fmaxf(a0.w + f1.y, 0.f);
                s1.x += fmaxf(a1.x + f2.x, 0.f);
                s1.y += fmaxf(a1.y + f2.y, 0.f);
                s1.z += fmaxf(a1.z + f3.x, 0.f);
                s1.w += fmaxf(a1.w + f3.y, 0.f);
            }
        }
        for (; t < cnt; t++) {
            int j = __shfl_sync(0xFFFFFFFFu, jv, t);
            uint4 pw = *(const uint4*)(g_Bh + (size_t)j * (D_H / 2) + bcolw);
            float2 f0 = u32_as_f2(pw.x);
            float2 f1 = u32_as_f2(pw.y);
            float2 f2 = u32_as_f2(pw.z);
            float2 f3 = u32_as_f2(pw.w);
            s0.x += fmaxf(a0.x + f0.x, 0.f);
            s0.y += fmaxf(a0.y + f0.y, 0.f);
            s0.z += fmaxf(a0.z + f1.x, 0.f);
            s0.w += fmaxf(a0.w + f1.y, 0.f);
            s1.x += fmaxf(a1.x + f2.x, 0.f);
            s1.y += fmaxf(a1.y + f2.y, 0.f);
            s1.z += fmaxf(a1.z + f3.x, 0.f);
            s1.w += fmaxf(a1.w + f3.y, 0.f);
        }
    }

    uint4 h;
    h.x = pack2h(s0.x, s0.y); h.y = pack2h(s0.z, s0.w);
    h.z = pack2h(s1.x, s1.y); h.w = pack2h(s1.z, s1.w);
    *(uint4*)(g_Sh + (size_t)node * (D_H / 2) + half * 128 + lane * 4) = h;
}

// ---------------- launcher --------------------------------------------------
extern "C" void kernel_launch(void* const* d_in, const int* in_sizes, int n_in,
                              void* d_out, int out_size) {
    const float* x   = (const float*)d_in[0];
    const void*  ei  = d_in[1];
    const float* W1  = (const float*)d_in[2];
    const float* b1  = (const float*)d_in[3];
    const float* W2  = (const float*)d_in[4];
    const float* b2  = (const float*)d_in[5];
    float* out = (float*)d_out;

    cudaFuncSetAttribute(tc_gemm_kernel,
                         cudaFuncAttributeMaxDynamicSharedMemorySize, GEMM_DYNSMEM);

    float *gA, *gB1;
    uint32_t *gXh, *gXl, *gW1h, *gW2h, *gSh, *gBh;
    int* gCounts;
    cudaGetSymbolAddress((void**)&gA,   g_Apart);
    cudaGetSymbolAddress((void**)&gBh,  g_Bh);
    cudaGetSymbolAddress((void**)&gB1,  g_bias1);
    cudaGetSymbolAddress((void**)&gXh,  g_Xh);
    cudaGetSymbolAddress((void**)&gXl,  g_Xl);
    cudaGetSymbolAddress((void**)&gW1h, g_W1h);
    cudaGetSymbolAddress((void**)&gW2h, g_W2h);
    cudaGetSymbolAddress((void**)&gSh,  g_Sh);
    cudaGetSymbolAddress((void**)&gCounts, g_counts);

    // launch order keeps GEMM1 in the 4th kernel slot (ncu capture)
    detect_dtype_kernel<<<1, 32>>>((const unsigned*)ei);
    split_x_kernel<<<(N_NODES * 32 + 255) / 256, 256>>>(x);
    build_w1t_kernel<<<(D_AB * (D_F / 2) + 255) / 256, 256>>>(W1, b1);

    // GEMM1 (4th): [A | B] = x @ WT1^T (+bias); A->fp32, B->fp16; 2-term A
    {
        dim3 grid(D_AB / 128, N_PAD / 128);
        tc_gemm_kernel<<<grid, 256, GEMM_DYNSMEM>>>(
            gXh, gXl, gW1h, gA, gBh, N_NODES, D_F, D_H, gB1, 0, 1);
    }

    cudaMemsetAsync(gCounts, 0, N_NODES * sizeof(int));
    hist_kernel<<<(N_EDGES + 255) / 256, 256>>>(ei);
    scan_kernel<<<1, 1024>>>();
    scatter_kernel<<<(N_EDGES + 255) / 256, 256>>>(ei);

    aggregate_kernel<<<(N_NODES * 2 * 32 + 255) / 256, 256>>>();
    build_w2t_kernel<<<(D_O * (D_H / 2) + 255) / 256, 256>>>(W2);

    // GEMM2: out[50000,256] = S @ W2^T + deg*b2; 1-term A (S single fp16)
    {
        dim3 grid(D_O / 128, N_PAD / 128);
        tc_gemm_kernel<<<grid, 256, GEMM_DYNSMEM>>>(
            gSh, nullptr, gW2h, out, nullptr, N_NODES, D_H, D_O, b2, 1, 0);
    }
}

// round 15
// speedup vs baseline: 1.2490x; 1.2490x over previous
#include <cuda_runtime.h>
#include <cuda_bf16.h>
#include <cuda_fp16.h>
#include <cstdint>

#define N_NODES 50000
#define N_PAD   50048      // padded to multiple of 128
#define N_EDGES 800000
#define D_F 256
#define D_H 512
#define D_O 256
#define D_AB 1024

// ---------------- scratch (static device allocations; no cudaMalloc) -------
__device__ uint32_t g_Xh[N_PAD * (D_F / 2)];       // packed fp16 x hi
__device__ uint32_t g_Xl[N_PAD * (D_F / 2)];       // packed fp16 x lo (residual)
__device__ uint32_t g_W1h[D_AB * (D_F / 2)];       // packed fp16 Wcat (single)
__device__ uint32_t g_W2h[D_O * (D_H / 2)];        // packed fp16 W2 (single)
__device__ float    g_bias1[D_AB];
__device__ float    g_Apart[N_PAD * D_H];          // 102.4 MB fp32 (A part)
__device__ uint32_t g_Bh[N_PAD * (D_H / 2)];       // 51.2 MB packed fp16 (B part)
__device__ uint32_t g_Sh[N_PAD * (D_H / 2)];       // S single fp16
__device__ int      g_counts[N_NODES];
__device__ int      g_offsets[N_NODES + 1];
__device__ int      g_cursor[N_NODES];
__device__ int      g_scol[N_EDGES];
__device__ int      g_idx64;

// ---------------- helpers ---------------------------------------------------
__device__ __forceinline__ uint32_t h2_as_u32(__half2 h) {
    uint32_t u; *(__half2*)&u = h; return u;
}
__device__ __forceinline__ float2 u32_as_f2(uint32_t u) {
    __half2 h = *(__half2*)&u;
    return __half22float2(h);
}
__device__ __forceinline__ void split2h(float v0, float v1, uint32_t& hw, uint32_t& lw) {
    __half2 hh = __floats2half2_rn(v0, v1);
    float2 back = __half22float2(hh);
    __half2 ll = __floats2half2_rn(v0 - back.x, v1 - back.y);
    hw = h2_as_u32(hh);
    lw = h2_as_u32(ll);
}
__device__ __forceinline__ uint32_t pack2h(float v0, float v1) {
    return h2_as_u32(__floats2half2_rn(v0, v1));
}
__device__ __forceinline__ void mma_f16(float* d, const uint32_t* a, const uint32_t* b) {
    asm volatile(
        "mma.sync.aligned.m16n8k16.row.col.f32.f16.f16.f32 "
        "{%0,%1,%2,%3}, {%4,%5,%6,%7}, {%8,%9}, {%0,%1,%2,%3};\n"
        : "+f"(d[0]), "+f"(d[1]), "+f"(d[2]), "+f"(d[3])
        : "r"(a[0]), "r"(a[1]), "r"(a[2]), "r"(a[3]), "r"(b[0]), "r"(b[1]));
}
__device__ __forceinline__ void ldsm_x4(uint32_t* r, uint32_t saddr) {
    asm volatile("ldmatrix.sync.aligned.m8n8.x4.shared.b16 {%0,%1,%2,%3}, [%4];"
                 : "=r"(r[0]), "=r"(r[1]), "=r"(r[2]), "=r"(r[3]) : "r"(saddr));
}
__device__ __forceinline__ uint32_t smem_u32(const void* p) {
    uint32_t a;
    asm("{ .reg .u64 t; cvta.to.shared.u64 t, %1; cvt.u32.u64 %0, t; }" : "=r"(a) : "l"(p));
    return a;
}
#define CP16(dst, src) \
    asm volatile("cp.async.cg.shared.global [%0], [%1], 16;" :: "r"(dst), "l"(src))
#define CP_COMMIT() asm volatile("cp.async.commit_group;" ::: "memory")
#define CP_WAIT0()  asm volatile("cp.async.wait_group 0;" ::: "memory")

// ---------------- edge-index dtype detection -------------------------------
__global__ void detect_dtype_kernel(const unsigned* ei) {
    unsigned acc = 0;
    for (int k = threadIdx.x; k < 512; k += 32) acc |= ei[2 * k + 1];
    #pragma unroll
    for (int o = 16; o > 0; o >>= 1) acc |= __shfl_xor_sync(0xFFFFFFFFu, acc, o);
    if (threadIdx.x == 0) g_idx64 = (acc == 0) ? 1 : 0;
}
__device__ __forceinline__ int load_eidx(const void* ei, int is64, long long pos) {
    return is64 ? (int)((const long long*)ei)[pos] : ((const int*)ei)[pos];
}

// ---------------- x split: fp32 -> packed fp16 hi/lo ------------------------
__global__ void split_x_kernel(const float* __restrict__ x) {
    int gid = blockIdx.x * blockDim.x + threadIdx.x;
    if (gid >= N_NODES * 32) return;
    int row = gid >> 5, ch = gid & 31;
    const float4* p = (const float4*)(x + (size_t)row * D_F + ch * 8);
    float4 v0 = p[0], v1 = p[1];
    uint4 h, l;
    split2h(v0.x, v0.y, h.x, l.x); split2h(v0.z, v0.w, h.y, l.y);
    split2h(v1.x, v1.y, h.z, l.z); split2h(v1.z, v1.w, h.w, l.w);
    *(uint4*)(g_Xh + (size_t)row * (D_F / 2) + ch * 4) = h;
    *(uint4*)(g_Xl + (size_t)row * (D_F / 2) + ch * 4) = l;
}

// ---------------- weight prep: K-major packed fp16 (single) ----------------
__global__ void build_w1t_kernel(const float* __restrict__ W1, const float* __restrict__ b1) {
    int idx = blockIdx.x * blockDim.x + threadIdx.x;
    if (idx < D_AB * (D_F / 2)) {
        int n  = idx >> 7;
        int kw = idx & 127;
        int k0 = kw * 2;
        float v0, v1;
        if (n < D_H) {
            v0 = W1[k0 * D_H + n]       - W1[(k0 + D_F) * D_H + n];
            v1 = W1[(k0 + 1) * D_H + n] - W1[(k0 + 1 + D_F) * D_H + n];
        } else {
            v0 = W1[(k0 + D_F) * D_H + (n - D_H)];
            v1 = W1[(k0 + 1 + D_F) * D_H + (n - D_H)];
        }
        g_W1h[idx] = pack2h(v0, v1);
    }
    if (idx < D_AB) g_bias1[idx] = (idx < D_H) ? b1[idx] : 0.f;
}
__global__ void build_w2t_kernel(const float* __restrict__ W2) {
    int idx = blockIdx.x * blockDim.x + threadIdx.x;
    if (idx < D_O * (D_H / 2)) {
        int n  = idx >> 8;
        int kw = idx & 255;
        g_W2h[idx] = pack2h(W2[(2 * kw) * D_O + n], W2[(2 * kw + 1) * D_O + n]);
    }
}

// ---------------- counting sort of edges by center node --------------------
__global__ void hist_kernel(const void* __restrict__ ei) {
    int e = blockIdx.x * blockDim.x + threadIdx.x;
    if (e >= N_EDGES) return;
    int r = load_eidx(ei, g_idx64, e);
    atomicAdd(&g_counts[r], 1);
}
__global__ void scan_kernel() {
    __shared__ int sh[1024];
    const int PER = 49;
    int t = threadIdx.x;
    int base = t * PER;
    int sum = 0;
    for (int j = 0; j < PER; j++) {
        int idx = base + j;
        if (idx < N_NODES) sum += g_counts[idx];
    }
    sh[t] = sum;
    __syncthreads();
    #pragma unroll
    for (int off = 1; off < 1024; off <<= 1) {
        int add = (t >= off) ? sh[t - off] : 0;
        __syncthreads();
        sh[t] += add;
        __syncthreads();
    }
    int run = sh[t] - sum;
    for (int j = 0; j < PER; j++) {
        int idx = base + j;
        if (idx < N_NODES) {
            g_offsets[idx] = run;
            g_cursor[idx]  = run;
            run += g_counts[idx];
        }
    }
    if (t == 1023) g_offsets[N_NODES] = run;
}
__global__ void scatter_kernel(const void* __restrict__ ei) {
    int e = blockIdx.x * blockDim.x + threadIdx.x;
    if (e >= N_EDGES) return;
    int is64 = g_idx64;
    int r = load_eidx(ei, is64, e);
    int c = load_eidx(ei, is64, (long long)N_EDGES + e);
    int pos = atomicAdd(&g_cursor[r], 1);
    g_scol[pos] = c;
}

// =========== fp16 GEMM (R13 config — frozen: BK=32, 2-stage, STW=20) =======
// C = (Ah[+Al]) @ W^T.
// mode 0 (GEMM1): cols < 512 -> fp32 C, cols >= 512 -> packed fp16 Cb.
// mode 1 (GEMM2): fp32 C with deg*bias.
#define KWC 16
#define STW 20
#define TILE_W (128 * STW)
#define STAGE_W (3 * TILE_W)
#define CSTRIDE 132
#define GEMM_DYNSMEM (CSTRIDE * 128 * 4)   // 67584 >= 2*STAGE_W*4 = 61440

__global__ void __launch_bounds__(256, 2) tc_gemm_kernel(
    const uint32_t* __restrict__ Ah, const uint32_t* __restrict__ Al,
    const uint32_t* __restrict__ Bs,
    float* __restrict__ C, uint32_t* __restrict__ Cb,
    int M, int K, int ldc,
    const float* __restrict__ bias, int mode, int aTwo)
{
    extern __shared__ uint32_t smw[];
    int tid = threadIdx.x;
    int wid = tid >> 5;
    int lane = tid & 31;
    int warpM = wid & 1;
    int warpN = wid >> 1;
    int blockRow = blockIdx.y * 128;
    int blockCol = blockIdx.x * 128;
    const int Kw = K >> 1;
    const int nch = K >> 5;

    float acc[4][4][4];
    #pragma unroll
    for (int mt = 0; mt < 4; mt++)
        #pragma unroll
        for (int nt = 0; nt < 4; nt++)
            #pragma unroll
            for (int r = 0; r < 4; r++) acc[mt][nt][r] = 0.f;

    uint32_t sbase = smem_u32(smw);
    int ldRow = tid >> 1;
    int ldHalf = tid & 1;
    uint32_t soB = (uint32_t)(ldRow * STW + ldHalf * 8) * 4;
    size_t aOff = (size_t)(blockRow + ldRow) * Kw + ldHalf * 8;
    size_t bOff = (size_t)(blockCol + ldRow) * Kw + ldHalf * 8;

    auto issue = [&](int c) {
        uint32_t d = sbase + (uint32_t)(c & 1) * (STAGE_W * 4) + soB;
        const uint32_t* a0 = Ah + aOff + (size_t)c * KWC;
        const uint32_t* b0 = Bs + bOff + (size_t)c * KWC;
        CP16(d, a0);                      CP16(d + 16, a0 + 4);
        if (aTwo) {
            const uint32_t* a1 = Al + aOff + (size_t)c * KWC;
            CP16(d + TILE_W * 4, a1);     CP16(d + TILE_W * 4 + 16, a1 + 4);
        }
        CP16(d + 2 * TILE_W * 4, b0);     CP16(d + 2 * TILE_W * 4 + 16, b0 + 4);
        CP_COMMIT();
    };

    issue(0);
    CP_WAIT0();
    __syncthreads();

    int aLaneRow = (lane & 7) + ((lane >> 3) & 1) * 8;
    int aLaneColW = (lane >> 4) * 4;
    int bLaneRow = (lane & 7) + (lane >> 4) * 8;
    int bLaneColW = ((lane >> 3) & 1) * 4;
    uint32_t aAddr0 = sbase + ((warpM * 64 + aLaneRow) * STW + aLaneColW) * 4;
    uint32_t bAddr0 = sbase + ((warpN * 32 + bLaneRow) * STW + bLaneColW) * 4
                      + 2 * TILE_W * 4;

    for (int c = 0; c < nch; c++) {
        if (c + 1 < nch) issue(c + 1);

        uint32_t stageOff = (uint32_t)(c & 1) * (STAGE_W * 4);
        #pragma unroll
        for (int ks = 0; ks < 2; ks++) {
            uint32_t kOff = stageOff + ks * 32;
            uint32_t ah[4][4], al[4][4], bs[2][4];
            #pragma unroll
            for (int mt = 0; mt < 4; mt++) {
                uint32_t a = aAddr0 + kOff + mt * (16 * STW * 4);
                ldsm_x4(ah[mt], a);
                if (aTwo) ldsm_x4(al[mt], a + TILE_W * 4);
            }
            #pragma unroll
            for (int p = 0; p < 2; p++) {
                uint32_t b = bAddr0 + kOff + p * (16 * STW * 4);
                ldsm_x4(bs[p], b);
            }
            #pragma unroll
            for (int mt = 0; mt < 4; mt++)
                #pragma unroll
                for (int nt = 0; nt < 4; nt++) {
                    const uint32_t* bh = &bs[nt >> 1][(nt & 1) * 2];
                    mma_f16(acc[mt][nt], ah[mt], bh);
                    if (aTwo) mma_f16(acc[mt][nt], al[mt], bh);
                }
        }

        if (c + 1 < nch) {
            CP_WAIT0();
            __syncthreads();
        }
    }

    // ---- staged epilogue: acc -> smem (fp32) -> coalesced gmem ----
    __syncthreads();
    float* cs = (float*)smw;
    #pragma unroll
    for (int mt = 0; mt < 4; mt++) {
        int r0 = warpM * 64 + mt * 16 + (lane >> 2);
        #pragma unroll
        for (int nt = 0; nt < 4; nt++) {
            int col = warpN * 32 + nt * 8 + (lane & 3) * 2;
            *(float2*)(cs + r0 * CSTRIDE + col) = make_float2(acc[mt][nt][0], acc[mt][nt][1]);
            *(float2*)(cs + (r0 + 8) * CSTRIDE + col) = make_float2(acc[mt][nt][2], acc[mt][nt][3]);
        }
    }
    __syncthreads();
    #pragma unroll
    for (int kk = 0; kk < 16; kk++) {
        int idx = tid + kk * 256;
        int row = idx >> 5;
        int c4 = (idx & 31) * 4;
        int gr = blockRow + row;
        if (gr < M) {
            float4 v = *(float4*)(cs + row * CSTRIDE + c4);
            int col = blockCol + c4;
            float4 bv = *(const float4*)(bias + col);
            if (mode == 0) {
                v.x += bv.x; v.y += bv.y; v.z += bv.z; v.w += bv.w;
                if (col < D_H) {
                    *(float4*)(C + (size_t)gr * ldc + col) = v;
                } else {
                    uint32_t w0 = h2_as_u32(__floats2half2_rn(v.x, v.y));
                    uint32_t w1 = h2_as_u32(__floats2half2_rn(v.z, v.w));
                    *(uint2*)(Cb + (size_t)gr * (D_H / 2) + ((col - D_H) >> 1)) =
                        make_uint2(w0, w1);
                }
            } else {
                float degf = (float)(g_offsets[gr + 1] - g_offsets[gr]);
                v.x += degf * bv.x; v.y += degf * bv.y;
                v.z += degf * bv.z; v.w += degf * bv.w;
                *(float4*)(C + (size_t)gr * ldc + col) = v;
            }
        }
    }
}

// ---------------- aggregation: 2 warps per node, fp16 B gathers -------------
// output: single fp16 packed S
__global__ void __launch_bounds__(256) aggregate_kernel() {
    int gwarp = (blockIdx.x * blockDim.x + threadIdx.x) >> 5;
    int node = gwarp >> 1;
    int half = gwarp & 1;
    int lane = threadIdx.x & 31;
    if (node >= N_NODES) return;

    const float* Abase = g_Apart + (size_t)node * D_H + half * 256 + lane * 8;
    float4 a0 = *(const float4*)Abase;
    float4 a1 = *(const float4*)(Abase + 4);
    float4 s0 = make_float4(0, 0, 0, 0), s1 = s0;

    const size_t bcolw = (size_t)(half * 128 + lane * 4);
    int beg = g_offsets[node], end = g_offsets[node + 1];

    for (int b = beg; b < end; b += 32) {
        int jv = (b + lane < end) ? g_scol[b + lane] : 0;
        int cnt = min(32, end - b);
        int t = 0;
        for (; t + 7 < cnt; t += 8) {
            uint4 pw[8];
            #pragma unroll
            for (int u = 0; u < 8; u++) {
                int j = __shfl_sync(0xFFFFFFFFu, jv, t + u);
                pw[u] = *(const uint4*)(g_Bh + (size_t)j * (D_H / 2) + bcolw);
            }
            #pragma unroll
            for (int u = 0; u < 8; u++) {
                float2 f0 = u32_as_f2(pw[u].x);
                float2 f1 = u32_as_f2(pw[u].y);
                float2 f2 = u32_as_f2(pw[u].z);
                float2 f3 = u32_as_f2(pw[u].w);
                s0.x += fmaxf(a0.x + f0.x, 0.f);
                s0.y += fmaxf(a0.y + f0.y, 0.f);
                s0.z += fmaxf(a0.z + f1.x, 0.f);
                s0.w += fmaxf(a0.w + f1.y, 0.f);
                s1.x += fmaxf(a1.x + f2.x, 0.f);
                s1.y += fmaxf(a1.y + f2.y, 0.f);
                s1.z += fmaxf(a1.z + f3.x, 0.f);
                s1.w += fmaxf(a1.w + f3.y, 0.f);
            }
        }
        for (; t < cnt; t++) {
            int j = __shfl_sync(0xFFFFFFFFu, jv, t);
            uint4 pw = *(const uint4*)(g_Bh + (size_t)j * (D_H / 2) + bcolw);
            float2 f0 = u32_as_f2(pw.x);
            float2 f1 = u32_as_f2(pw.y);
            float2 f2 = u32_as_f2(pw.z);
            float2 f3 = u32_as_f2(pw.w);
            s0.x += fmaxf(a0.x + f0.x, 0.f);
            s0.y += fmaxf(a0.y + f0.y, 0.f);
            s0.z += fmaxf(a0.z + f1.x, 0.f);
            s0.w += fmaxf(a0.w + f1.y, 0.f);
            s1.x += fmaxf(a1.x + f2.x, 0.f);
            s1.y += fmaxf(a1.y + f2.y, 0.f);
            s1.z += fmaxf(a1.z + f3.x, 0.f);
            s1.w += fmaxf(a1.w + f3.y, 0.f);
        }
    }

    uint4 h;
    h.x = pack2h(s0.x, s0.y); h.y = pack2h(s0.z, s0.w);
    h.z = pack2h(s1.x, s1.y); h.w = pack2h(s1.z, s1.w);
    *(uint4*)(g_Sh + (size_t)node * (D_H / 2) + half * 128 + lane * 4) = h;
}

// ---------------- launcher --------------------------------------------------
static cudaStream_t g_s2 = nullptr;
static cudaEvent_t  g_evFork = nullptr;
static cudaEvent_t  g_evJoin = nullptr;

extern "C" void kernel_launch(void* const* d_in, const int* in_sizes, int n_in,
                              void* d_out, int out_size) {
    const float* x   = (const float*)d_in[0];
    const void*  ei  = d_in[1];
    const float* W1  = (const float*)d_in[2];
    const float* b1  = (const float*)d_in[3];
    const float* W2  = (const float*)d_in[4];
    const float* b2  = (const float*)d_in[5];
    float* out = (float*)d_out;

    if (!g_s2) {   // first call is the uncaptured correctness run
        cudaStreamCreateWithFlags(&g_s2, cudaStreamNonBlocking);
        cudaEventCreateWithFlags(&g_evFork, cudaEventDisableTiming);
        cudaEventCreateWithFlags(&g_evJoin, cudaEventDisableTiming);
        cudaFuncSetAttribute(tc_gemm_kernel,
                             cudaFuncAttributeMaxDynamicSharedMemorySize, GEMM_DYNSMEM);
    }

    float *gA, *gB1;
    uint32_t *gXh, *gXl, *gW1h, *gW2h, *gSh, *gBh;
    int* gCounts;
    cudaGetSymbolAddress((void**)&gA,   g_Apart);
    cudaGetSymbolAddress((void**)&gBh,  g_Bh);
    cudaGetSymbolAddress((void**)&gB1,  g_bias1);
    cudaGetSymbolAddress((void**)&gXh,  g_Xh);
    cudaGetSymbolAddress((void**)&gXl,  g_Xl);
    cudaGetSymbolAddress((void**)&gW1h, g_W1h);
    cudaGetSymbolAddress((void**)&gW2h, g_W2h);
    cudaGetSymbolAddress((void**)&gSh,  g_Sh);
    cudaGetSymbolAddress((void**)&gCounts, g_counts);

    // ---- main stream: detect -> (fork) -> split_x -> w1t -> GEMM1 ----
    detect_dtype_kernel<<<1, 32>>>((const unsigned*)ei);
    cudaEventRecord(g_evFork, 0);
    split_x_kernel<<<(N_NODES * 32 + 255) / 256, 256>>>(x);
    build_w1t_kernel<<<(D_AB * (D_F / 2) + 255) / 256, 256>>>(W1, b1);

    // GEMM1 (4th launch slot): [A | B] = x @ WT1^T (+bias); 2-term A
    {
        dim3 grid(D_AB / 128, N_PAD / 128);
        tc_gemm_kernel<<<grid, 256, GEMM_DYNSMEM>>>(
            gXh, gXl, gW1h, gA, gBh, N_NODES, D_F, D_H, gB1, 0, 1);
    }

    // ---- side stream: edge sort chain (independent of GEMM1) ----
    cudaStreamWaitEvent(g_s2, g_evFork, 0);
    cudaMemsetAsync(gCounts, 0, N_NODES * sizeof(int), g_s2);
    hist_kernel<<<(N_EDGES + 255) / 256, 256, 0, g_s2>>>(ei);
    scan_kernel<<<1, 1024, 0, g_s2>>>();
    scatter_kernel<<<(N_EDGES + 255) / 256, 256, 0, g_s2>>>(ei);
    cudaEventRecord(g_evJoin, g_s2);

    // ---- join, then aggregate -> w2t -> GEMM2 on main stream ----
    cudaStreamWaitEvent(0, g_evJoin, 0);
    aggregate_kernel<<<(N_NODES * 2 * 32 + 255) / 256, 256>>>();
    build_w2t_kernel<<<(D_O * (D_H / 2) + 255) / 256, 256>>>(W2);

    // GEMM2: out = S @ W2^T + deg*b2; 1-term A (S single fp16)
    {
        dim3 grid(D_O / 128, N_PAD / 128);
        tc_gemm_kernel<<<grid, 256, GEMM_DYNSMEM>>>(
            gSh, nullptr, gW2h, out, nullptr, N_NODES, D_H, D_O, b2, 1, 0);
    }
}

// round 17
// speedup vs baseline: 1.2589x; 1.0079x over previous
#include <cuda_runtime.h>
#include <cuda_bf16.h>
#include <cuda_fp16.h>
#include <cstdint>

#define N_NODES 50000
#define N_PAD   50048      // padded to multiple of 128
#define N_EDGES 800000
#define D_F 256
#define D_H 512
#define D_O 256
#define D_AB 1024

// ---------------- scratch (static device allocations; no cudaMalloc) -------
__device__ uint32_t g_Xh[N_PAD * (D_F / 2)];       // packed fp16 x hi
__device__ uint32_t g_Xl[N_PAD * (D_F / 2)];       // packed fp16 x lo (residual)
__device__ uint32_t g_W1h[D_AB * (D_F / 2)];       // packed fp16 Wcat (single)
__device__ uint32_t g_W2h[D_O * (D_H / 2)];        // packed fp16 W2 (single)
__device__ float    g_bias1[D_AB];
__device__ uint32_t g_Ah[N_PAD * (D_H / 2)];       // 51.2 MB packed fp16 (A part)
__device__ uint32_t g_Bh[N_PAD * (D_H / 2)];       // 51.2 MB packed fp16 (B part)
__device__ uint32_t g_Sh[N_PAD * (D_H / 2)];       // S single fp16
__device__ int      g_counts[N_NODES];
__device__ int      g_offsets[N_NODES + 1];
__device__ int      g_cursor[N_NODES];
__device__ int      g_scol[N_EDGES];
__device__ int      g_idx64;

// ---------------- helpers ---------------------------------------------------
__device__ __forceinline__ uint32_t h2_as_u32(__half2 h) {
    uint32_t u; *(__half2*)&u = h; return u;
}
__device__ __forceinline__ float2 u32_as_f2(uint32_t u) {
    __half2 h = *(__half2*)&u;
    return __half22float2(h);
}
__device__ __forceinline__ void split2h(float v0, float v1, uint32_t& hw, uint32_t& lw) {
    __half2 hh = __floats2half2_rn(v0, v1);
    float2 back = __half22float2(hh);
    __half2 ll = __floats2half2_rn(v0 - back.x, v1 - back.y);
    hw = h2_as_u32(hh);
    lw = h2_as_u32(ll);
}
__device__ __forceinline__ uint32_t pack2h(float v0, float v1) {
    return h2_as_u32(__floats2half2_rn(v0, v1));
}
__device__ __forceinline__ void mma_f16(float* d, const uint32_t* a, const uint32_t* b) {
    asm volatile(
        "mma.sync.aligned.m16n8k16.row.col.f32.f16.f16.f32 "
        "{%0,%1,%2,%3}, {%4,%5,%6,%7}, {%8,%9}, {%0,%1,%2,%3};\n"
        : "+f"(d[0]), "+f"(d[1]), "+f"(d[2]), "+f"(d[3])
        : "r"(a[0]), "r"(a[1]), "r"(a[2]), "r"(a[3]), "r"(b[0]), "r"(b[1]));
}
__device__ __forceinline__ void ldsm_x4(uint32_t* r, uint32_t saddr) {
    asm volatile("ldmatrix.sync.aligned.m8n8.x4.shared.b16 {%0,%1,%2,%3}, [%4];"
                 : "=r"(r[0]), "=r"(r[1]), "=r"(r[2]), "=r"(r[3]) : "r"(saddr));
}
__device__ __forceinline__ uint32_t smem_u32(const void* p) {
    uint32_t a;
    asm("{ .reg .u64 t; cvta.to.shared.u64 t, %1; cvt.u32.u64 %0, t; }" : "=r"(a) : "l"(p));
    return a;
}
#define CP16(dst, src) \
    asm volatile("cp.async.cg.shared.global [%0], [%1], 16;" :: "r"(dst), "l"(src))
#define CP_COMMIT() asm volatile("cp.async.commit_group;" ::: "memory")
#define CP_WAIT0()  asm volatile("cp.async.wait_group 0;" ::: "memory")

// ---------------- edge-index dtype detection -------------------------------
__global__ void detect_dtype_kernel(const unsigned* ei) {
    unsigned acc = 0;
    for (int k = threadIdx.x; k < 512; k += 32) acc |= ei[2 * k + 1];
    #pragma unroll
    for (int o = 16; o > 0; o >>= 1) acc |= __shfl_xor_sync(0xFFFFFFFFu, acc, o);
    if (threadIdx.x == 0) g_idx64 = (acc == 0) ? 1 : 0;
}
__device__ __forceinline__ int load_eidx(const void* ei, int is64, long long pos) {
    return is64 ? (int)((const long long*)ei)[pos] : ((const int*)ei)[pos];
}

// ---------------- x split: fp32 -> packed fp16 hi/lo ------------------------
__global__ void split_x_kernel(const float* __restrict__ x) {
    int gid = blockIdx.x * blockDim.x + threadIdx.x;
    if (gid >= N_NODES * 32) return;
    int row = gid >> 5, ch = gid & 31;
    const float4* p = (const float4*)(x + (size_t)row * D_F + ch * 8);
    float4 v0 = p[0], v1 = p[1];
    uint4 h, l;
    split2h(v0.x, v0.y, h.x, l.x); split2h(v0.z, v0.w, h.y, l.y);
    split2h(v1.x, v1.y, h.z, l.z); split2h(v1.z, v1.w, h.w, l.w);
    *(uint4*)(g_Xh + (size_t)row * (D_F / 2) + ch * 4) = h;
    *(uint4*)(g_Xl + (size_t)row * (D_F / 2) + ch * 4) = l;
}

// ---------------- weight prep: K-major packed fp16 (single) ----------------
__global__ void build_w1t_kernel(const float* __restrict__ W1, const float* __restrict__ b1) {
    int idx = blockIdx.x * blockDim.x + threadIdx.x;
    if (idx < D_AB * (D_F / 2)) {
        int n  = idx >> 7;
        int kw = idx & 127;
        int k0 = kw * 2;
        float v0, v1;
        if (n < D_H) {
            v0 = W1[k0 * D_H + n]       - W1[(k0 + D_F) * D_H + n];
            v1 = W1[(k0 + 1) * D_H + n] - W1[(k0 + 1 + D_F) * D_H + n];
        } else {
            v0 = W1[(k0 + D_F) * D_H + (n - D_H)];
            v1 = W1[(k0 + 1 + D_F) * D_H + (n - D_H)];
        }
        g_W1h[idx] = pack2h(v0, v1);
    }
    if (idx < D_AB) g_bias1[idx] = (idx < D_H) ? b1[idx] : 0.f;
}
__global__ void build_w2t_kernel(const float* __restrict__ W2) {
    int idx = blockIdx.x * blockDim.x + threadIdx.x;
    if (idx < D_O * (D_H / 2)) {
        int n  = idx >> 8;
        int kw = idx & 255;
        g_W2h[idx] = pack2h(W2[(2 * kw) * D_O + n], W2[(2 * kw + 1) * D_O + n]);
    }
}

// ---------------- counting sort of edges by center node --------------------
__global__ void hist_kernel(const void* __restrict__ ei) {
    int e = blockIdx.x * blockDim.x + threadIdx.x;
    if (e >= N_EDGES) return;
    int r = load_eidx(ei, g_idx64, e);
    atomicAdd(&g_counts[r], 1);
}
__global__ void scan_kernel() {
    __shared__ int sh[1024];
    const int PER = 49;
    int t = threadIdx.x;
    int base = t * PER;
    int sum = 0;
    for (int j = 0; j < PER; j++) {
        int idx = base + j;
        if (idx < N_NODES) sum += g_counts[idx];
    }
    sh[t] = sum;
    __syncthreads();
    #pragma unroll
    for (int off = 1; off < 1024; off <<= 1) {
        int add = (t >= off) ? sh[t - off] : 0;
        __syncthreads();
        sh[t] += add;
        __syncthreads();
    }
    int run = sh[t] - sum;
    for (int j = 0; j < PER; j++) {
        int idx = base + j;
        if (idx < N_NODES) {
            g_offsets[idx] = run;
            g_cursor[idx]  = run;
            run += g_counts[idx];
        }
    }
    if (t == 1023) g_offsets[N_NODES] = run;
}
__global__ void scatter_kernel(const void* __restrict__ ei) {
    int e = blockIdx.x * blockDim.x + threadIdx.x;
    if (e >= N_EDGES) return;
    int is64 = g_idx64;
    int r = load_eidx(ei, is64, e);
    int c = load_eidx(ei, is64, (long long)N_EDGES + e);
    int pos = atomicAdd(&g_cursor[r], 1);
    g_scol[pos] = c;
}

// =========== fp16 GEMM (R13 config — frozen: BK=32, 2-stage, STW=20) =======
// C = (Ah[+Al]) @ W^T.
// mode 0 (GEMM1): cols < 512 -> packed fp16 Ca, cols >= 512 -> packed fp16 Cb.
// mode 1 (GEMM2): fp32 C with deg*bias.
#define KWC 16
#define STW 20
#define TILE_W (128 * STW)
#define STAGE_W (3 * TILE_W)
#define CSTRIDE 132
#define GEMM_DYNSMEM (CSTRIDE * 128 * 4)   // 67584 >= 2*STAGE_W*4 = 61440

__global__ void __launch_bounds__(256, 2) tc_gemm_kernel(
    const uint32_t* __restrict__ Ah, const uint32_t* __restrict__ Al,
    const uint32_t* __restrict__ Bs,
    float* __restrict__ C, uint32_t* __restrict__ Ca, uint32_t* __restrict__ Cb,
    int M, int K, int ldc,
    const float* __restrict__ bias, int mode, int aTwo)
{
    extern __shared__ uint32_t smw[];
    int tid = threadIdx.x;
    int wid = tid >> 5;
    int lane = tid & 31;
    int warpM = wid & 1;
    int warpN = wid >> 1;
    int blockRow = blockIdx.y * 128;
    int blockCol = blockIdx.x * 128;
    const int Kw = K >> 1;
    const int nch = K >> 5;

    float acc[4][4][4];
    #pragma unroll
    for (int mt = 0; mt < 4; mt++)
        #pragma unroll
        for (int nt = 0; nt < 4; nt++)
            #pragma unroll
            for (int r = 0; r < 4; r++) acc[mt][nt][r] = 0.f;

    uint32_t sbase = smem_u32(smw);
    int ldRow = tid >> 1;
    int ldHalf = tid & 1;
    uint32_t soB = (uint32_t)(ldRow * STW + ldHalf * 8) * 4;
    size_t aOff = (size_t)(blockRow + ldRow) * Kw + ldHalf * 8;
    size_t bOff = (size_t)(blockCol + ldRow) * Kw + ldHalf * 8;

    auto issue = [&](int c) {
        uint32_t d = sbase + (uint32_t)(c & 1) * (STAGE_W * 4) + soB;
        const uint32_t* a0 = Ah + aOff + (size_t)c * KWC;
        const uint32_t* b0 = Bs + bOff + (size_t)c * KWC;
        CP16(d, a0);                      CP16(d + 16, a0 + 4);
        if (aTwo) {
            const uint32_t* a1 = Al + aOff + (size_t)c * KWC;
            CP16(d + TILE_W * 4, a1);     CP16(d + TILE_W * 4 + 16, a1 + 4);
        }
        CP16(d + 2 * TILE_W * 4, b0);     CP16(d + 2 * TILE_W * 4 + 16, b0 + 4);
        CP_COMMIT();
    };

    issue(0);
    CP_WAIT0();
    __syncthreads();

    int aLaneRow = (lane & 7) + ((lane >> 3) & 1) * 8;
    int aLaneColW = (lane >> 4) * 4;
    int bLaneRow = (lane & 7) + (lane >> 4) * 8;
    int bLaneColW = ((lane >> 3) & 1) * 4;
    uint32_t aAddr0 = sbase + ((warpM * 64 + aLaneRow) * STW + aLaneColW) * 4;
    uint32_t bAddr0 = sbase + ((warpN * 32 + bLaneRow) * STW + bLaneColW) * 4
                      + 2 * TILE_W * 4;

    for (int c = 0; c < nch; c++) {
        if (c + 1 < nch) issue(c + 1);

        uint32_t stageOff = (uint32_t)(c & 1) * (STAGE_W * 4);
        #pragma unroll
        for (int ks = 0; ks < 2; ks++) {
            uint32_t kOff = stageOff + ks * 32;
            uint32_t ah[4][4], al[4][4], bs[2][4];
            #pragma unroll
            for (int mt = 0; mt < 4; mt++) {
                uint32_t a = aAddr0 + kOff + mt * (16 * STW * 4);
                ldsm_x4(ah[mt], a);
                if (aTwo) ldsm_x4(al[mt], a + TILE_W * 4);
            }
            #pragma unroll
            for (int p = 0; p < 2; p++) {
                uint32_t b = bAddr0 + kOff + p * (16 * STW * 4);
                ldsm_x4(bs[p], b);
            }
            #pragma unroll
            for (int mt = 0; mt < 4; mt++)
                #pragma unroll
                for (int nt = 0; nt < 4; nt++) {
                    const uint32_t* bh = &bs[nt >> 1][(nt & 1) * 2];
                    mma_f16(acc[mt][nt], ah[mt], bh);
                    if (aTwo) mma_f16(acc[mt][nt], al[mt], bh);
                }
        }

        if (c + 1 < nch) {
            CP_WAIT0();
            __syncthreads();
        }
    }

    // ---- staged epilogue: acc -> smem (fp32) -> coalesced gmem ----
    __syncthreads();
    float* cs = (float*)smw;
    #pragma unroll
    for (int mt = 0; mt < 4; mt++) {
        int r0 = warpM * 64 + mt * 16 + (lane >> 2);
        #pragma unroll
        for (int nt = 0; nt < 4; nt++) {
            int col = warpN * 32 + nt * 8 + (lane & 3) * 2;
            *(float2*)(cs + r0 * CSTRIDE + col) = make_float2(acc[mt][nt][0], acc[mt][nt][1]);
            *(float2*)(cs + (r0 + 8) * CSTRIDE + col) = make_float2(acc[mt][nt][2], acc[mt][nt][3]);
        }
    }
    __syncthreads();
    #pragma unroll
    for (int kk = 0; kk < 16; kk++) {
        int idx = tid + kk * 256;
        int row = idx >> 5;
        int c4 = (idx & 31) * 4;
        int gr = blockRow + row;
        if (gr < M) {
            float4 v = *(float4*)(cs + row * CSTRIDE + c4);
            int col = blockCol + c4;
            float4 bv = *(const float4*)(bias + col);
            if (mode == 0) {
                v.x += bv.x; v.y += bv.y; v.z += bv.z; v.w += bv.w;
                uint32_t w0 = pack2h(v.x, v.y);
                uint32_t w1 = pack2h(v.z, v.w);
                if (col < D_H) {
                    *(uint2*)(Ca + (size_t)gr * (D_H / 2) + (col >> 1)) =
                        make_uint2(w0, w1);
                } else {
                    *(uint2*)(Cb + (size_t)gr * (D_H / 2) + ((col - D_H) >> 1)) =
                        make_uint2(w0, w1);
                }
            } else {
                float degf = (float)(g_offsets[gr + 1] - g_offsets[gr]);
                v.x += degf * bv.x; v.y += degf * bv.y;
                v.z += degf * bv.z; v.w += degf * bv.w;
                *(float4*)(C + (size_t)gr * ldc + col) = v;
            }
        }
    }
}

// ---------------- aggregation: 2 warps per node, fp16 A+B -------------------
// output: single fp16 packed S
__global__ void __launch_bounds__(256) aggregate_kernel() {
    int gwarp = (blockIdx.x * blockDim.x + threadIdx.x) >> 5;
    int node = gwarp >> 1;
    int half = gwarp & 1;
    int lane = threadIdx.x & 31;
    if (node >= N_NODES) return;

    const size_t rowoff = (size_t)(half * 128 + lane * 4);
    uint4 aw = *(const uint4*)(g_Ah + (size_t)node * (D_H / 2) + rowoff);
    float2 A0 = u32_as_f2(aw.x), A1 = u32_as_f2(aw.y);
    float2 A2 = u32_as_f2(aw.z), A3 = u32_as_f2(aw.w);
    float4 a0 = make_float4(A0.x, A0.y, A1.x, A1.y);
    float4 a1 = make_float4(A2.x, A2.y, A3.x, A3.y);
    float4 s0 = make_float4(0, 0, 0, 0), s1 = s0;

    int beg = g_offsets[node], end = g_offsets[node + 1];

    for (int b = beg; b < end; b += 32) {
        int jv = (b + lane < end) ? g_scol[b + lane] : 0;
        int cnt = min(32, end - b);
        int t = 0;
        for (; t + 7 < cnt; t += 8) {
            uint4 pw[8];
            #pragma unroll
            for (int u = 0; u < 8; u++) {
                int j = __shfl_sync(0xFFFFFFFFu, jv, t + u);
                pw[u] = *(const uint4*)(g_Bh + (size_t)j * (D_H / 2) + rowoff);
            }
            #pragma unroll
            for (int u = 0; u < 8; u++) {
                float2 f0 = u32_as_f2(pw[u].x);
                float2 f1 = u32_as_f2(pw[u].y);
                float2 f2 = u32_as_f2(pw[u].z);
                float2 f3 = u32_as_f2(pw[u].w);
                s0.x += fmaxf(a0.x + f0.x, 0.f);
                s0.y += fmaxf(a0.y + f0.y, 0.f);
                s0.z += fmaxf(a0.z + f1.x, 0.f);
                s0.w += fmaxf(a0.w + f1.y, 0.f);
                s1.x += fmaxf(a1.x + f2.x, 0.f);
                s1.y += fmaxf(a1.y + f2.y, 0.f);
                s1.z += fmaxf(a1.z + f3.x, 0.f);
                s1.w += fmaxf(a1.w + f3.y, 0.f);
            }
        }
        for (; t < cnt; t++) {
            int j = __shfl_sync(0xFFFFFFFFu, jv, t);
            uint4 pw = *(const uint4*)(g_Bh + (size_t)j * (D_H / 2) + rowoff);
            float2 f0 = u32_as_f2(pw.x);
            float2 f1 = u32_as_f2(pw.y);
            float2 f2 = u32_as_f2(pw.z);
            float2 f3 = u32_as_f2(pw.w);
            s0.x += fmaxf(a0.x + f0.x, 0.f);
            s0.y += fmaxf(a0.y + f0.y, 0.f);
            s0.z += fmaxf(a0.z + f1.x, 0.f);
            s0.w += fmaxf(a0.w + f1.y, 0.f);
            s1.x += fmaxf(a1.x + f2.x, 0.f);
            s1.y += fmaxf(a1.y + f2.y, 0.f);
            s1.z += fmaxf(a1.z + f3.x, 0.f);
            s1.w += fmaxf(a1.w + f3.y, 0.f);
        }
    }

    uint4 h;
    h.x = pack2h(s0.x, s0.y); h.y = pack2h(s0.z, s0.w);
    h.z = pack2h(s1.x, s1.y); h.w = pack2h(s1.z, s1.w);
    *(uint4*)(g_Sh + (size_t)node * (D_H / 2) + rowoff) = h;
}

// ---------------- launcher --------------------------------------------------
static cudaStream_t g_s2 = nullptr;
static cudaEvent_t  g_evFork = nullptr;
static cudaEvent_t  g_evJoin = nullptr;

extern "C" void kernel_launch(void* const* d_in, const int* in_sizes, int n_in,
                              void* d_out, int out_size) {
    const float* x   = (const float*)d_in[0];
    const void*  ei  = d_in[1];
    const float* W1  = (const float*)d_in[2];
    const float* b1  = (const float*)d_in[3];
    const float* W2  = (const float*)d_in[4];
    const float* b2  = (const float*)d_in[5];
    float* out = (float*)d_out;

    if (!g_s2) {   // first call is the uncaptured correctness run
        cudaStreamCreateWithFlags(&g_s2, cudaStreamNonBlocking);
        cudaEventCreateWithFlags(&g_evFork, cudaEventDisableTiming);
        cudaEventCreateWithFlags(&g_evJoin, cudaEventDisableTiming);
        cudaFuncSetAttribute(tc_gemm_kernel,
                             cudaFuncAttributeMaxDynamicSharedMemorySize, GEMM_DYNSMEM);
    }

    float* gB1;
    uint32_t *gXh, *gXl, *gW1h, *gW2h, *gSh, *gAh, *gBh;
    int* gCounts;
    cudaGetSymbolAddress((void**)&gAh,  g_Ah);
    cudaGetSymbolAddress((void**)&gBh,  g_Bh);
    cudaGetSymbolAddress((void**)&gB1,  g_bias1);
    cudaGetSymbolAddress((void**)&gXh,  g_Xh);
    cudaGetSymbolAddress((void**)&gXl,  g_Xl);
    cudaGetSymbolAddress((void**)&gW1h, g_W1h);
    cudaGetSymbolAddress((void**)&gW2h, g_W2h);
    cudaGetSymbolAddress((void**)&gSh,  g_Sh);
    cudaGetSymbolAddress((void**)&gCounts, g_counts);

    // ---- main stream: detect -> (fork) -> split_x -> w1t -> GEMM1 ----
    detect_dtype_kernel<<<1, 32>>>((const unsigned*)ei);
    cudaEventRecord(g_evFork, 0);
    split_x_kernel<<<(N_NODES * 32 + 255) / 256, 256>>>(x);
    build_w1t_kernel<<<(D_AB * (D_F / 2) + 255) / 256, 256>>>(W1, b1);

    // GEMM1 (4th launch slot): [A | B] = x @ WT1^T (+bias); 2-term A; fp16 out
    {
        dim3 grid(D_AB / 128, N_PAD / 128);
        tc_gemm_kernel<<<grid, 256, GEMM_DYNSMEM>>>(
            gXh, gXl, gW1h, nullptr, gAh, gBh, N_NODES, D_F, D_H, gB1, 0, 1);
    }

    // ---- side stream: edge sort chain + w2t (independent of GEMM1) ----
    cudaStreamWaitEvent(g_s2, g_evFork, 0);
    cudaMemsetAsync(gCounts, 0, N_NODES * sizeof(int), g_s2);
    hist_kernel<<<(N_EDGES + 255) / 256, 256, 0, g_s2>>>(ei);
    scan_kernel<<<1, 1024, 0, g_s2>>>();
    scatter_kernel<<<(N_EDGES + 255) / 256, 256, 0, g_s2>>>(ei);
    build_w2t_kernel<<<(D_O * (D_H / 2) + 255) / 256, 256, 0, g_s2>>>(W2);
    cudaEventRecord(g_evJoin, g_s2);

    // ---- join, then aggregate -> GEMM2 on main stream ----
    cudaStreamWaitEvent(0, g_evJoin, 0);
    aggregate_kernel<<<(N_NODES * 2 * 32 + 255) / 256, 256>>>();

    // GEMM2: out = S @ W2^T + deg*b2; 1-term A (S single fp16)
    {
        dim3 grid(D_O / 128, N_PAD / 128);
        tc_gemm_kernel<<<grid, 256, GEMM_DYNSMEM>>>(
            gSh, nullptr, gW2h, out, nullptr, nullptr, N_NODES, D_H, D_O, b2, 1, 0);
    }
}